// round 8
// baseline (speedup 1.0000x reference)
#include <cuda_runtime.h>
#include <cuda_bf16.h>
#include <math.h>

#define BB   16
#define NN   128
#define FIN  128
#define FOUT 256
#define EOUT 64
#define BIN  14
#define BOUT 64
#define CI   64
#define LL1  256
#define CATW (2*CI + FOUT)   // 384
#define RPB  16

typedef unsigned long long ull;

// ---------------- scratch ----------------
__device__ float d_h  [BB*NN*FOUT];
__device__ float d_hc [BB*NN];
__device__ float d_s1 [BB*NN];
__device__ float d_s2 [BB*NN];
__device__ float d_ee [BB*NN*NN];
__device__ float d_att[BB*NN*NN];
__device__ float d_hn [BB*NN*NN];
__device__ float d_pre[2][BB*NN*CI];
__device__ float d_cat[BB*NN*CATW];

__device__ __forceinline__ float lrelu(float v) { return v > 0.f ? v : 0.01f * v; }

// ---- packed fp32x2 helpers ----
__device__ __forceinline__ ull pk(float lo, float hi) {
    ull r; asm("mov.b64 %0, {%1,%2};" : "=l"(r) : "f"(lo), "f"(hi)); return r;
}
__device__ __forceinline__ void fma2(ull& d, ull a, ull b) {
    asm("fma.rn.f32x2 %0, %1, %2, %3;" : "=l"(d) : "l"(a), "l"(b), "l"(d));
}
__device__ __forceinline__ ull add2(ull a, ull b) {
    ull r; asm("add.rn.f32x2 %0, %1, %2;" : "=l"(r) : "l"(a), "l"(b)); return r;
}
__device__ __forceinline__ float2 upk(ull v) {
    float2 f; asm("mov.b64 {%0,%1}, %2;" : "=f"(f.x), "=f"(f.y) : "l"(v)); return f;
}
__device__ __forceinline__ float hsum2(ull v) { float2 p = upk(v); return p.x + p.y; }
__device__ __forceinline__ float wred(float v) {
    #pragma unroll
    for (int off = 16; off > 0; off >>= 1) v += __shfl_xor_sync(0xffffffffu, v, off);
    return v;
}

// ============ K1: blocks [0,128): h=x@W, ha=h@a, s1/s2/hc ; [128,1152): wsum =======
__global__ void __launch_bounds__(256) K1(const float* __restrict__ x,
                                          const float* __restrict__ W,
                                          const float* __restrict__ a,
                                          const float* __restrict__ w_edge,
                                          const float* __restrict__ wfc_w,
                                          const float* __restrict__ wfc_b,
                                          const float* __restrict__ fc_w,
                                          const float* __restrict__ fcc_w) {
    __shared__ __align__(16) float smem_u[RPB*FIN + RPB*FOUT];   // 24 KB
    int tid = threadIdx.x;
    if (blockIdx.x < 128) {
        int f    = tid;
        int row0 = blockIdx.x * RPB;
        float* xs = smem_u;
        float* hs = smem_u + RPB*FIN;
        {
            const float4* src = reinterpret_cast<const float4*>(x + row0*FIN);
            float4* dst = reinterpret_cast<float4*>(xs);
            for (int t = f; t < RPB*FIN/4; t += 256) dst[t] = src[t];
        }
        __syncthreads();
        {
            ull acc[RPB];
            #pragma unroll
            for (int r = 0; r < RPB; r++) acc[r] = 0ull;
            #pragma unroll 2
            for (int kq = 0; kq < FIN/4; kq++) {
                float w0 = W[(4*kq+0)*FOUT + f];
                float w1 = W[(4*kq+1)*FOUT + f];
                float w2 = W[(4*kq+2)*FOUT + f];
                float w3 = W[(4*kq+3)*FOUT + f];
                ull wp0 = pk(w0, w1), wp1 = pk(w2, w3);
                #pragma unroll
                for (int r = 0; r < RPB; r++) {
                    ulonglong2 xv = *reinterpret_cast<const ulonglong2*>(&xs[r*FIN + 4*kq]);
                    fma2(acc[r], xv.x, wp0);
                    fma2(acc[r], xv.y, wp1);
                }
            }
            #pragma unroll
            for (int r = 0; r < RPB; r++) {
                float v = hsum2(acc[r]);
                hs[r*FOUT + f] = v;
                d_h[(row0+r)*FOUT + f] = v;
            }
        }
        __syncthreads();
        float* ha1s = xs;
        float* ha2s = xs + RPB*EOUT;
        {
            int g  = f >> 6;
            int kp = f & 63;
            int half = g >> 1;
            int r0 = (g & 1) * 8;
            const float* ap = a + half*FOUT*EOUT + kp;
            ull acc[8];
            #pragma unroll
            for (int r = 0; r < 8; r++) acc[r] = 0ull;
            #pragma unroll 2
            for (int fq = 0; fq < FOUT/4; fq++) {
                float w0 = ap[(4*fq+0)*EOUT];
                float w1 = ap[(4*fq+1)*EOUT];
                float w2 = ap[(4*fq+2)*EOUT];
                float w3 = ap[(4*fq+3)*EOUT];
                ull wp0 = pk(w0, w1), wp1 = pk(w2, w3);
                #pragma unroll
                for (int r = 0; r < 8; r++) {
                    ulonglong2 hv = *reinterpret_cast<const ulonglong2*>(&hs[(r0+r)*FOUT + 4*fq]);
                    fma2(acc[r], hv.x, wp0);
                    fma2(acc[r], hv.y, wp1);
                }
            }
            float* has = half ? ha2s : ha1s;
            #pragma unroll
            for (int r = 0; r < 8; r++)
                has[(r0 + r)*EOUT + kp] = hsum2(acc[r]);
        }
        __syncthreads();
        {
            int warp = tid >> 5, lane = tid & 31;
            if (warp < 4) {
                float fw0 = fc_w[lane], fw1 = fc_w[32 + lane];
                #pragma unroll
                for (int rr = 0; rr < 4; rr++) {
                    int r = warp*4 + rr;
                    float v = lrelu(ha1s[r*EOUT + lane]      + ha2s[r*EOUT + lane])      * fw0
                            + lrelu(ha1s[r*EOUT + 32 + lane] + ha2s[r*EOUT + 32 + lane]) * fw1;
                    v = wred(v);
                    if (lane == 0) d_s1[row0 + r] = v;
                }
            } else if (warp < 6) {
                float fw0 = fc_w[lane], fw1 = fc_w[32 + lane];
                int b  = row0 >> 7;
                int j0 = ((row0 & 127) >> 1);
                #pragma unroll
                for (int q = 0; q < 4; q++) {
                    int jj = (warp - 4)*4 + q;
                    int r1 = 2*jj, r2 = 2*jj + 1;
                    float v = lrelu(ha1s[r1*EOUT + lane]      + ha2s[r2*EOUT + lane])      * fw0
                            + lrelu(ha1s[r1*EOUT + 32 + lane] + ha2s[r2*EOUT + 32 + lane]) * fw1;
                    v = wred(v);
                    if (lane == 0) {
                        d_s2[b*NN + j0 + jj]      = v;
                        d_s2[b*NN + j0 + jj + 64] = v;
                    }
                }
            } else {
                #pragma unroll
                for (int rr = 0; rr < 8; rr++) {
                    int r = (warp - 6)*8 + rr;
                    float v = 0.f;
                    #pragma unroll
                    for (int q = 0; q < 8; q++)
                        v += hs[r*FOUT + lane + 32*q] * fcc_w[lane + 32*q];
                    v = wred(v);
                    if (lane == 0) d_hc[row0 + r] = v;
                }
            }
        }
    } else {
        int w    = blockIdx.x - 128;
        int row0 = w * 2;
        float* wes = smem_u;
        float* wf  = smem_u + 2*NN*BIN;
        float* wb  = wf + BIN*BOUT;
        float* f2  = wb + BOUT;
        {
            const float4* src = reinterpret_cast<const float4*>(w_edge + (size_t)row0*NN*BIN);
            float4* dst = reinterpret_cast<float4*>(wes);
            for (int t = tid; t < 2*NN*BIN/4; t += 256) dst[t] = src[t];
        }
        for (int t = tid; t < BIN*BOUT; t += 256) wf[t] = wfc_w[t];
        if (tid < BOUT) { wb[tid] = wfc_b[tid]; f2[tid] = fc_w[BOUT + tid]; }
        __syncthreads();

        int r = tid >> 7, j = tid & 127;
        ull we2[BIN];
        #pragma unroll
        for (int m = 0; m < BIN; m++) { float v = wes[(r*NN + j)*BIN + m]; we2[m] = pk(v, v); }

        const ulonglong2* wfp = reinterpret_cast<const ulonglong2*>(wf);
        const ulonglong2* wbp = reinterpret_cast<const ulonglong2*>(wb);
        const float4*     f2p = reinterpret_cast<const float4*>(f2);
        float wsum = 0.f;
        #pragma unroll 4
        for (int kq = 0; kq < BOUT/4; kq++) {
            ulonglong2 aq = wbp[kq];
            ull a0 = aq.x, a1 = aq.y;
            #pragma unroll
            for (int m = 0; m < BIN; m++) {
                ulonglong2 w2 = wfp[m*16 + kq];
                fma2(a0, we2[m], w2.x);
                fma2(a1, we2[m], w2.y);
            }
            float2 p0 = upk(a0), p1 = upk(a1);
            float4 fv = f2p[kq];
            wsum += lrelu(p0.x)*fv.x + lrelu(p0.y)*fv.y + lrelu(p1.x)*fv.z + lrelu(p1.y)*fv.w;
        }
        d_ee[(row0 + r)*NN + j] = wsum;
    }
}

// ---------------- K4b: mask + softmax + hn ----------------
__global__ void __launch_bounds__(NN) k4b(const int* __restrict__ adj,
                                          const float* __restrict__ fc_b,
                                          const float* __restrict__ fcc_b)
{
    int bi = blockIdx.x;
    int b = bi >> 7, i = bi & 127;
    int j = threadIdx.x;
    float contrib = (i < 64) ? d_s1[b*NN + 2*i + (j >= 64 ? 1 : 0)]
                             : d_s2[b*NN + j];
    float e = d_ee[(size_t)bi*NN + j] + contrib + fc_b[0];
    if (adj[(size_t)bi*NN + j] <= 0) e = -9e15f;

    int lane = j & 31, wid = j >> 5;
    float mx = e;
    #pragma unroll
    for (int off = 16; off > 0; off >>= 1) mx = fmaxf(mx, __shfl_xor_sync(0xffffffffu, mx, off));
    __shared__ float wredm[4], wreds[4];
    if (lane == 0) wredm[wid] = mx;
    __syncthreads();
    mx = fmaxf(fmaxf(wredm[0], wredm[1]), fmaxf(wredm[2], wredm[3]));
    float ex = __expf(e - mx);
    float s = ex;
    #pragma unroll
    for (int off = 16; off > 0; off >>= 1) s += __shfl_xor_sync(0xffffffffu, s, off);
    if (lane == 0) wreds[wid] = s;
    __syncthreads();
    s = (wreds[0] + wreds[1]) + (wreds[2] + wreds[3]);
    float att = ex / s;

    d_att[(size_t)bi*NN + j] = att;
    d_hn [(size_t)bi*NN + j] = lrelu(att * d_hc[bi] + fcc_b[0]);
}

// ---------------- KB: blocks [0,256): h1 = att@h (8 rows); [256,512): RNN pre ------
__global__ void __launch_bounds__(256) kB(
    const float* __restrict__ wih_f, const float* __restrict__ bih_f,
    const float* __restrict__ bhh_f,
    const float* __restrict__ wih_b, const float* __restrict__ bih_b,
    const float* __restrict__ bhh_b)
{
    __shared__ __align__(16) float pool[NN*65 + RPB*NN];
    int tid = threadIdx.x;
    if (blockIdx.x < 256) {
        int bx = blockIdx.x;
        int b  = bx >> 4;
        int i0 = (bx & 15) * 8;
        float* as = pool;
        for (int idx = tid; idx < 8*NN; idx += 256)
            as[idx] = d_att[((size_t)b*NN + i0)*NN + idx];
        __syncthreads();
        ull acc[8];
        #pragma unroll
        for (int r = 0; r < 8; r++) acc[r] = 0ull;
        const float* hb = d_h + b*NN*FOUT;
        #pragma unroll 2
        for (int jq = 0; jq < NN/4; jq++) {
            float h0 = hb[(4*jq+0)*FOUT + tid];
            float h1 = hb[(4*jq+1)*FOUT + tid];
            float h2 = hb[(4*jq+2)*FOUT + tid];
            float h3 = hb[(4*jq+3)*FOUT + tid];
            ull hp0 = pk(h0, h1), hp1 = pk(h2, h3);
            #pragma unroll
            for (int r = 0; r < 8; r++) {
                ulonglong2 av = *reinterpret_cast<const ulonglong2*>(&as[r*NN + 4*jq]);
                fma2(acc[r], av.x, hp0);
                fma2(acc[r], av.y, hp1);
            }
        }
        #pragma unroll
        for (int r = 0; r < 8; r++)
            d_cat[(b*NN + i0 + r)*CATW + 2*CI + tid] = hsum2(acc[r]);
    } else {
        int bx2 = blockIdx.x - 256;
        int dir = bx2 >> 7;
        int rem = bx2 & 127;
        int b   = rem >> 3;
        int t0  = (rem & 7) * RPB;
        int c    = tid & 63;
        int quad = tid >> 6;
        float* wT = pool;
        float* xs = pool + NN*65;
        const float* wih = dir ? wih_b : wih_f;
        for (int idx = tid; idx < CI*NN; idx += 256) {
            int cc = idx >> 7, q = idx & 127;
            wT[q*65 + cc] = wih[idx];
        }
        for (int idx = tid; idx < RPB*NN; idx += 256) {
            int r = idx >> 7, q = idx & 127;
            int src = dir ? (NN-1 - (t0+r)) : (t0+r);
            xs[r*NN + q] = d_hn[(b*NN + src)*NN + q];
        }
        __syncthreads();
        float bias = dir ? (bih_b[c] + bhh_b[c]) : (bih_f[c] + bhh_f[c]);
        float acc[4];
        #pragma unroll
        for (int r = 0; r < 4; r++) acc[r] = bias;
        #pragma unroll 2
        for (int qq = 0; qq < NN/4; qq++) {
            float w0 = wT[(4*qq+0)*65 + c];
            float w1 = wT[(4*qq+1)*65 + c];
            float w2 = wT[(4*qq+2)*65 + c];
            float w3 = wT[(4*qq+3)*65 + c];
            #pragma unroll
            for (int r = 0; r < 4; r++) {
                float4 xv = *reinterpret_cast<const float4*>(&xs[(quad*4+r)*NN + 4*qq]);
                acc[r] = fmaf(xv.x, w0, fmaf(xv.y, w1, fmaf(xv.z, w2, fmaf(xv.w, w3, acc[r]))));
            }
        }
        #pragma unroll
        for (int r = 0; r < 4; r++)
            d_pre[dir][(b*NN + t0 + quad*4 + r)*CI + c] = acc[r];
    }
}

// ---------------- K6: serial RNN — 2 threads per hidden unit, smem-only loop -------
__global__ void __launch_bounds__(128) k6_rnn(const float* __restrict__ whh_f,
                                              const float* __restrict__ whh_b)
{
    __shared__ __align__(16) float ps[NN*CI];      // 32 KB: pre slab, then lrelu out
    __shared__ __align__(16) float hbuf[2][CI];
    int dir = blockIdx.x >> 4;
    int b   = blockIdx.x & 15;
    int tid = threadIdx.x;                 // 128
    int j    = tid >> 1;                   // hidden unit
    int half = tid & 1;                    // which 32-chunk of the dot
    const float* whh = dir ? whh_b : whh_f;
    ull w2[16];
    {
        const float4* wr = reinterpret_cast<const float4*>(whh + j*64 + half*32);
        #pragma unroll
        for (int kk = 0; kk < 8; kk++) {
            float4 wv = wr[kk];
            w2[2*kk]   = pk(wv.x, wv.y);
            w2[2*kk+1] = pk(wv.z, wv.w);
        }
    }
    {
        const float4* src = reinterpret_cast<const float4*>(d_pre[dir] + (size_t)b*NN*CI);
        float4* dst = reinterpret_cast<float4*>(ps);
        #pragma unroll
        for (int t = tid; t < NN*CI/4; t += 128) dst[t] = src[t];
    }
    if (half == 0) hbuf[0][j] = 0.f;
    __syncthreads();
    #pragma unroll 1
    for (int t = 0; t < NN; t++) {
        int cur = t & 1;
        float pv = ps[t*CI + j];
        const ulonglong2* h4 = reinterpret_cast<const ulonglong2*>(hbuf[cur] + half*32);
        ull a0 = 0ull, a1 = 0ull, a2 = 0ull, a3 = 0ull;
        #pragma unroll
        for (int kk = 0; kk < 8; kk++) {
            ulonglong2 hv = h4[kk];
            ull& acc = (kk & 3) == 0 ? a0 : ((kk & 3) == 1 ? a1 : ((kk & 3) == 2 ? a2 : a3));
            fma2(acc, w2[2*kk],   hv.x);
            fma2(acc, w2[2*kk+1], hv.y);
        }
        float dot = hsum2(add2(add2(a0, a1), add2(a2, a3)));
        dot += __shfl_xor_sync(0xffffffffu, dot, 1);   // combine partner half
        float sarg = pv + dot;
        float ee = __expf(2.f * sarg);
        float th = 1.f - __fdividef(2.f, ee + 1.f);
        if (half == 0) hbuf[cur ^ 1][j] = th;          // recurrence state
        else           ps[t*CI + j] = lrelu(th);       // output (overwrite consumed)
        __syncthreads();
    }
    // bulk coalesced writeback
    float* base = d_cat + (size_t)(b*NN)*CATW + dir*CI;
    #pragma unroll 4
    for (int q = tid; q < NN*CI; q += 128) {
        int t = q >> 6, jj = q & 63;
        int tt = dir ? (NN-1 - t) : t;
        base[tt*CATW + jj] = ps[q];
    }
}

// ---------------- K8: out = elu(cat @ fco_w + fco_b) ----------------
__global__ void __launch_bounds__(256) k8_out(const float* __restrict__ fco_w,
                                              const float* __restrict__ fco_b,
                                              float* __restrict__ out)
{
    int c    = threadIdx.x;
    int row0 = blockIdx.x * RPB;
    __shared__ __align__(16) float cs[RPB*CATW];
    {
        const float4* src = reinterpret_cast<const float4*>(d_cat + row0*CATW);
        float4* dst = reinterpret_cast<float4*>(cs);
        for (int t = c; t < RPB*CATW/4; t += 256) dst[t] = src[t];
    }
    __syncthreads();
    float bias = fco_b[c];
    ull acc[RPB];
    #pragma unroll
    for (int r = 0; r < RPB; r++) acc[r] = 0ull;
    #pragma unroll 2
    for (int qq = 0; qq < CATW/4; qq++) {
        float w0 = fco_w[(4*qq+0)*LL1 + c];
        float w1 = fco_w[(4*qq+1)*LL1 + c];
        float w2 = fco_w[(4*qq+2)*LL1 + c];
        float w3 = fco_w[(4*qq+3)*LL1 + c];
        ull wp0 = pk(w0, w1), wp1 = pk(w2, w3);
        #pragma unroll
        for (int r = 0; r < RPB; r++) {
            ulonglong2 cv = *reinterpret_cast<const ulonglong2*>(&cs[r*CATW + 4*qq]);
            fma2(acc[r], cv.x, wp0);
            fma2(acc[r], cv.y, wp1);
        }
    }
    #pragma unroll
    for (int r = 0; r < RPB; r++) {
        float v = hsum2(acc[r]) + bias;
        out[(row0+r)*LL1 + c] = v > 0.f ? v : expm1f(v);
    }
}

// ---------------- launch ----------------
extern "C" void kernel_launch(void* const* d_in, const int* in_sizes, int n_in,
                              void* d_out, int out_size)
{
    const float* x     = (const float*)d_in[0];
    const int*   adj   = (const int*)  d_in[1];
    const float* wedge = (const float*)d_in[2];
    const float* W     = (const float*)d_in[3];
    const float* a     = (const float*)d_in[4];
    const float* wfc_w = (const float*)d_in[5];
    const float* wfc_b = (const float*)d_in[6];
    const float* fc_w  = (const float*)d_in[7];
    const float* fc_b  = (const float*)d_in[8];
    const float* fcc_w = (const float*)d_in[9];
    const float* fcc_b = (const float*)d_in[10];
    const float* wih_f = (const float*)d_in[11];
    const float* whh_f = (const float*)d_in[12];
    const float* bih_f = (const float*)d_in[13];
    const float* bhh_f = (const float*)d_in[14];
    const float* wih_b = (const float*)d_in[15];
    const float* whh_b = (const float*)d_in[16];
    const float* bih_b = (const float*)d_in[17];
    const float* bhh_b = (const float*)d_in[18];
    const float* fco_w = (const float*)d_in[19];
    const float* fco_b = (const float*)d_in[20];
    float* out = (float*)d_out;

    K1    <<<128 + 1024, 256>>>(x, W, a, wedge, wfc_w, wfc_b, fc_w, fcc_w);
    k4b   <<<BB*NN,       NN>>>(adj, fc_b, fcc_b);
    kB    <<<512,        256>>>(wih_f, bih_f, bhh_f, wih_b, bih_b, bhh_b);
    k6_rnn<<<2*BB,       128>>>(whh_f, whh_b);
    k8_out<<<BB*NN/RPB,  256>>>(fco_w, fco_b, out);
}

// round 9
// speedup vs baseline: 1.0046x; 1.0046x over previous
#include <cuda_runtime.h>
#include <cuda_bf16.h>
#include <math.h>

#define BB   16
#define NN   128
#define FIN  128
#define FOUT 256
#define EOUT 64
#define BIN  14
#define BOUT 64
#define CI   64
#define LL1  256
#define CATW (2*CI + FOUT)   // 384
#define RPB  16

typedef unsigned long long ull;

// ---------------- scratch ----------------
__device__ float d_h  [BB*NN*FOUT];
__device__ float d_hc [BB*NN];
__device__ float d_s1 [BB*NN];
__device__ float d_s2 [BB*NN];
__device__ float d_ee [BB*NN*NN];
__device__ float d_att[BB*NN*NN];
__device__ float d_hn [BB*NN*NN];
__device__ float d_pre[2][BB*NN*CI];
__device__ float d_cat[BB*NN*CATW];
__device__ float d_po [BB*NN*LL1];        // partial output (h1 part + bias)

__device__ __forceinline__ float lrelu(float v) { return v > 0.f ? v : 0.01f * v; }

// ---- packed fp32x2 helpers ----
__device__ __forceinline__ ull pk(float lo, float hi) {
    ull r; asm("mov.b64 %0, {%1,%2};" : "=l"(r) : "f"(lo), "f"(hi)); return r;
}
__device__ __forceinline__ void fma2(ull& d, ull a, ull b) {
    asm("fma.rn.f32x2 %0, %1, %2, %3;" : "=l"(d) : "l"(a), "l"(b), "l"(d));
}
__device__ __forceinline__ ull add2(ull a, ull b) {
    ull r; asm("add.rn.f32x2 %0, %1, %2;" : "=l"(r) : "l"(a), "l"(b)); return r;
}
__device__ __forceinline__ float2 upk(ull v) {
    float2 f; asm("mov.b64 {%0,%1}, %2;" : "=f"(f.x), "=f"(f.y) : "l"(v)); return f;
}
__device__ __forceinline__ float hsum2(ull v) { float2 p = upk(v); return p.x + p.y; }
__device__ __forceinline__ float wred(float v) {
    #pragma unroll
    for (int off = 16; off > 0; off >>= 1) v += __shfl_xor_sync(0xffffffffu, v, off);
    return v;
}

// ============ K1: blocks [0,128): h=x@W, ha=h@a, s1/s2/hc ; [128,1152): wsum =======
__global__ void __launch_bounds__(256) K1(const float* __restrict__ x,
                                          const float* __restrict__ W,
                                          const float* __restrict__ a,
                                          const float* __restrict__ w_edge,
                                          const float* __restrict__ wfc_w,
                                          const float* __restrict__ wfc_b,
                                          const float* __restrict__ fc_w,
                                          const float* __restrict__ fcc_w) {
    __shared__ __align__(16) float smem_u[RPB*FIN + RPB*FOUT];   // 24 KB
    int tid = threadIdx.x;
    if (blockIdx.x < 128) {
        int f    = tid;
        int row0 = blockIdx.x * RPB;
        float* xs = smem_u;
        float* hs = smem_u + RPB*FIN;
        {
            const float4* src = reinterpret_cast<const float4*>(x + row0*FIN);
            float4* dst = reinterpret_cast<float4*>(xs);
            for (int t = f; t < RPB*FIN/4; t += 256) dst[t] = src[t];
        }
        __syncthreads();
        {
            ull acc[RPB];
            #pragma unroll
            for (int r = 0; r < RPB; r++) acc[r] = 0ull;
            #pragma unroll 2
            for (int kq = 0; kq < FIN/4; kq++) {
                float w0 = W[(4*kq+0)*FOUT + f];
                float w1 = W[(4*kq+1)*FOUT + f];
                float w2 = W[(4*kq+2)*FOUT + f];
                float w3 = W[(4*kq+3)*FOUT + f];
                ull wp0 = pk(w0, w1), wp1 = pk(w2, w3);
                #pragma unroll
                for (int r = 0; r < RPB; r++) {
                    ulonglong2 xv = *reinterpret_cast<const ulonglong2*>(&xs[r*FIN + 4*kq]);
                    fma2(acc[r], xv.x, wp0);
                    fma2(acc[r], xv.y, wp1);
                }
            }
            #pragma unroll
            for (int r = 0; r < RPB; r++) {
                float v = hsum2(acc[r]);
                hs[r*FOUT + f] = v;
                d_h[(row0+r)*FOUT + f] = v;
            }
        }
        __syncthreads();
        float* ha1s = xs;
        float* ha2s = xs + RPB*EOUT;
        {
            int g  = f >> 6;
            int kp = f & 63;
            int half = g >> 1;
            int r0 = (g & 1) * 8;
            const float* ap = a + half*FOUT*EOUT + kp;
            ull acc[8];
            #pragma unroll
            for (int r = 0; r < 8; r++) acc[r] = 0ull;
            #pragma unroll 2
            for (int fq = 0; fq < FOUT/4; fq++) {
                float w0 = ap[(4*fq+0)*EOUT];
                float w1 = ap[(4*fq+1)*EOUT];
                float w2 = ap[(4*fq+2)*EOUT];
                float w3 = ap[(4*fq+3)*EOUT];
                ull wp0 = pk(w0, w1), wp1 = pk(w2, w3);
                #pragma unroll
                for (int r = 0; r < 8; r++) {
                    ulonglong2 hv = *reinterpret_cast<const ulonglong2*>(&hs[(r0+r)*FOUT + 4*fq]);
                    fma2(acc[r], hv.x, wp0);
                    fma2(acc[r], hv.y, wp1);
                }
            }
            float* has = half ? ha2s : ha1s;
            #pragma unroll
            for (int r = 0; r < 8; r++)
                has[(r0 + r)*EOUT + kp] = hsum2(acc[r]);
        }
        __syncthreads();
        {
            int warp = tid >> 5, lane = tid & 31;
            if (warp < 4) {
                float fw0 = fc_w[lane], fw1 = fc_w[32 + lane];
                #pragma unroll
                for (int rr = 0; rr < 4; rr++) {
                    int r = warp*4 + rr;
                    float v = lrelu(ha1s[r*EOUT + lane]      + ha2s[r*EOUT + lane])      * fw0
                            + lrelu(ha1s[r*EOUT + 32 + lane] + ha2s[r*EOUT + 32 + lane]) * fw1;
                    v = wred(v);
                    if (lane == 0) d_s1[row0 + r] = v;
                }
            } else if (warp < 6) {
                float fw0 = fc_w[lane], fw1 = fc_w[32 + lane];
                int b  = row0 >> 7;
                int j0 = ((row0 & 127) >> 1);
                #pragma unroll
                for (int q = 0; q < 4; q++) {
                    int jj = (warp - 4)*4 + q;
                    int r1 = 2*jj, r2 = 2*jj + 1;
                    float v = lrelu(ha1s[r1*EOUT + lane]      + ha2s[r2*EOUT + lane])      * fw0
                            + lrelu(ha1s[r1*EOUT + 32 + lane] + ha2s[r2*EOUT + 32 + lane]) * fw1;
                    v = wred(v);
                    if (lane == 0) {
                        d_s2[b*NN + j0 + jj]      = v;
                        d_s2[b*NN + j0 + jj + 64] = v;
                    }
                }
            } else {
                #pragma unroll
                for (int rr = 0; rr < 8; rr++) {
                    int r = (warp - 6)*8 + rr;
                    float v = 0.f;
                    #pragma unroll
                    for (int q = 0; q < 8; q++)
                        v += hs[r*FOUT + lane + 32*q] * fcc_w[lane + 32*q];
                    v = wred(v);
                    if (lane == 0) d_hc[row0 + r] = v;
                }
            }
        }
    } else {
        int w    = blockIdx.x - 128;
        int row0 = w * 2;
        float* wes = smem_u;
        float* wf  = smem_u + 2*NN*BIN;
        float* wb  = wf + BIN*BOUT;
        float* f2  = wb + BOUT;
        {
            const float4* src = reinterpret_cast<const float4*>(w_edge + (size_t)row0*NN*BIN);
            float4* dst = reinterpret_cast<float4*>(wes);
            for (int t = tid; t < 2*NN*BIN/4; t += 256) dst[t] = src[t];
        }
        for (int t = tid; t < BIN*BOUT; t += 256) wf[t] = wfc_w[t];
        if (tid < BOUT) { wb[tid] = wfc_b[tid]; f2[tid] = fc_w[BOUT + tid]; }
        __syncthreads();

        int r = tid >> 7, j = tid & 127;
        ull we2[BIN];
        #pragma unroll
        for (int m = 0; m < BIN; m++) { float v = wes[(r*NN + j)*BIN + m]; we2[m] = pk(v, v); }

        const ulonglong2* wfp = reinterpret_cast<const ulonglong2*>(wf);
        const ulonglong2* wbp = reinterpret_cast<const ulonglong2*>(wb);
        const float4*     f2p = reinterpret_cast<const float4*>(f2);
        float wsum = 0.f;
        #pragma unroll 4
        for (int kq = 0; kq < BOUT/4; kq++) {
            ulonglong2 aq = wbp[kq];
            ull a0 = aq.x, a1 = aq.y;
            #pragma unroll
            for (int m = 0; m < BIN; m++) {
                ulonglong2 w2 = wfp[m*16 + kq];
                fma2(a0, we2[m], w2.x);
                fma2(a1, we2[m], w2.y);
            }
            float2 p0 = upk(a0), p1 = upk(a1);
            float4 fv = f2p[kq];
            wsum += lrelu(p0.x)*fv.x + lrelu(p0.y)*fv.y + lrelu(p1.x)*fv.z + lrelu(p1.y)*fv.w;
        }
        d_ee[(row0 + r)*NN + j] = wsum;
    }
}

// ---------------- K4b: mask + softmax + hn ----------------
__global__ void __launch_bounds__(NN) k4b(const int* __restrict__ adj,
                                          const float* __restrict__ fc_b,
                                          const float* __restrict__ fcc_b)
{
    int bi = blockIdx.x;
    int b = bi >> 7, i = bi & 127;
    int j = threadIdx.x;
    float contrib = (i < 64) ? d_s1[b*NN + 2*i + (j >= 64 ? 1 : 0)]
                             : d_s2[b*NN + j];
    float e = d_ee[(size_t)bi*NN + j] + contrib + fc_b[0];
    if (adj[(size_t)bi*NN + j] <= 0) e = -9e15f;

    int lane = j & 31, wid = j >> 5;
    float mx = e;
    #pragma unroll
    for (int off = 16; off > 0; off >>= 1) mx = fmaxf(mx, __shfl_xor_sync(0xffffffffu, mx, off));
    __shared__ float wredm[4], wreds[4];
    if (lane == 0) wredm[wid] = mx;
    __syncthreads();
    mx = fmaxf(fmaxf(wredm[0], wredm[1]), fmaxf(wredm[2], wredm[3]));
    float ex = __expf(e - mx);
    float s = ex;
    #pragma unroll
    for (int off = 16; off > 0; off >>= 1) s += __shfl_xor_sync(0xffffffffu, s, off);
    if (lane == 0) wreds[wid] = s;
    __syncthreads();
    s = (wreds[0] + wreds[1]) + (wreds[2] + wreds[3]);
    float att = ex / s;

    d_att[(size_t)bi*NN + j] = att;
    d_hn [(size_t)bi*NN + j] = lrelu(att * d_hc[bi] + fcc_b[0]);
}

// ---------------- KB: blocks [0,256): h1 = att@h (8 rows); [256,512): RNN pre ------
__global__ void __launch_bounds__(256) kB(
    const float* __restrict__ wih_f, const float* __restrict__ bih_f,
    const float* __restrict__ bhh_f,
    const float* __restrict__ wih_b, const float* __restrict__ bih_b,
    const float* __restrict__ bhh_b)
{
    __shared__ __align__(16) float pool[NN*65 + RPB*NN];
    int tid = threadIdx.x;
    if (blockIdx.x < 256) {
        int bx = blockIdx.x;
        int b  = bx >> 4;
        int i0 = (bx & 15) * 8;
        float* as = pool;
        for (int idx = tid; idx < 8*NN; idx += 256)
            as[idx] = d_att[((size_t)b*NN + i0)*NN + idx];
        __syncthreads();
        ull acc[8];
        #pragma unroll
        for (int r = 0; r < 8; r++) acc[r] = 0ull;
        const float* hb = d_h + b*NN*FOUT;
        #pragma unroll 2
        for (int jq = 0; jq < NN/4; jq++) {
            float h0 = hb[(4*jq+0)*FOUT + tid];
            float h1 = hb[(4*jq+1)*FOUT + tid];
            float h2 = hb[(4*jq+2)*FOUT + tid];
            float h3 = hb[(4*jq+3)*FOUT + tid];
            ull hp0 = pk(h0, h1), hp1 = pk(h2, h3);
            #pragma unroll
            for (int r = 0; r < 8; r++) {
                ulonglong2 av = *reinterpret_cast<const ulonglong2*>(&as[r*NN + 4*jq]);
                fma2(acc[r], av.x, hp0);
                fma2(acc[r], av.y, hp1);
            }
        }
        #pragma unroll
        for (int r = 0; r < 8; r++)
            d_cat[(b*NN + i0 + r)*CATW + 2*CI + tid] = hsum2(acc[r]);
    } else {
        int bx2 = blockIdx.x - 256;
        int dir = bx2 >> 7;
        int rem = bx2 & 127;
        int b   = rem >> 3;
        int t0  = (rem & 7) * RPB;
        int c    = tid & 63;
        int quad = tid >> 6;
        float* wT = pool;
        float* xs = pool + NN*65;
        const float* wih = dir ? wih_b : wih_f;
        for (int idx = tid; idx < CI*NN; idx += 256) {
            int cc = idx >> 7, q = idx & 127;
            wT[q*65 + cc] = wih[idx];
        }
        for (int idx = tid; idx < RPB*NN; idx += 256) {
            int r = idx >> 7, q = idx & 127;
            int src = dir ? (NN-1 - (t0+r)) : (t0+r);
            xs[r*NN + q] = d_hn[(b*NN + src)*NN + q];
        }
        __syncthreads();
        float bias = dir ? (bih_b[c] + bhh_b[c]) : (bih_f[c] + bhh_f[c]);
        float acc[4];
        #pragma unroll
        for (int r = 0; r < 4; r++) acc[r] = bias;
        #pragma unroll 2
        for (int qq = 0; qq < NN/4; qq++) {
            float w0 = wT[(4*qq+0)*65 + c];
            float w1 = wT[(4*qq+1)*65 + c];
            float w2 = wT[(4*qq+2)*65 + c];
            float w3 = wT[(4*qq+3)*65 + c];
            #pragma unroll
            for (int r = 0; r < 4; r++) {
                float4 xv = *reinterpret_cast<const float4*>(&xs[(quad*4+r)*NN + 4*qq]);
                acc[r] = fmaf(xv.x, w0, fmaf(xv.y, w1, fmaf(xv.z, w2, fmaf(xv.w, w3, acc[r]))));
            }
        }
        #pragma unroll
        for (int r = 0; r < 4; r++)
            d_pre[dir][(b*NN + t0 + quad*4 + r)*CI + c] = acc[r];
    }
}

// ======= K6P: blocks [0,32): serial RNN (verbatim measured-best);
//         blocks [32,160): partial out d_po = fco_b + h1 @ fco_w[128:384]  =========
__global__ void __launch_bounds__(64) k6p(const float* __restrict__ whh_f,
                                          const float* __restrict__ whh_b,
                                          const float* __restrict__ fco_w,
                                          const float* __restrict__ fco_b)
{
    __shared__ __align__(16) float ps[NN*CI];      // 32 KB
    __shared__ __align__(16) float hbuf[2][CI];
    int tid = threadIdx.x;                          // 64
    if (blockIdx.x < 32) {
        // ---- serial RNN: 1 block per (dir, batch), smem slab, STG-in-loop ----
        int dir = blockIdx.x >> 4;
        int b   = blockIdx.x & 15;
        int j   = tid;
        const float* whh = dir ? whh_b : whh_f;
        ull w2[32];
        {
            const float4* wr = reinterpret_cast<const float4*>(whh + j*64);
            #pragma unroll
            for (int kk = 0; kk < 16; kk++) {
                float4 wv = wr[kk];
                w2[2*kk]   = pk(wv.x, wv.y);
                w2[2*kk+1] = pk(wv.z, wv.w);
            }
        }
        {
            const float4* src = reinterpret_cast<const float4*>(d_pre[dir] + (size_t)b*NN*CI);
            float4* dst = reinterpret_cast<float4*>(ps);
            #pragma unroll
            for (int t = j; t < NN*CI/4; t += 64) dst[t] = src[t];
        }
        hbuf[0][j] = 0.f;
        __syncthreads();
        float* outp = d_cat + (size_t)(b*NN)*CATW + dir*CI + j;
        #pragma unroll 1
        for (int t = 0; t < NN; t++) {
            int cur = t & 1;
            float pv = ps[t*CI + j];
            const ulonglong2* h4 = reinterpret_cast<const ulonglong2*>(hbuf[cur]);
            ull a0 = 0ull, a1 = 0ull, a2 = 0ull, a3 = 0ull;
            #pragma unroll
            for (int kk = 0; kk < 16; kk++) {
                ulonglong2 hv = h4[kk];
                ull& acc = (kk & 3) == 0 ? a0 : ((kk & 3) == 1 ? a1 : ((kk & 3) == 2 ? a2 : a3));
                fma2(acc, w2[2*kk],   hv.x);
                fma2(acc, w2[2*kk+1], hv.y);
            }
            float dot = hsum2(add2(add2(a0, a1), add2(a2, a3)));
            float sarg = pv + dot;
            float ee = __expf(2.f * sarg);
            float th = 1.f - __fdividef(2.f, ee + 1.f);
            hbuf[cur ^ 1][j] = th;
            int tt = dir ? (NN-1 - t) : t;
            outp[tt*CATW] = lrelu(th);
            __syncthreads();
        }
    } else {
        // ---- partial out: 16 rows per block ----
        int pb   = blockIdx.x - 32;        // 0..127
        int row0 = pb * 16;
        float* h1s = ps;                   // [256][20] padded (5120 floats <= 8192)
        for (int idx = tid; idx < 16*256; idx += 64) {
            int r = idx >> 8, q = idx & 255;
            h1s[q*20 + r] = d_cat[(size_t)(row0+r)*CATW + 2*CI + q];
        }
        __syncthreads();
        // acc[rp][c]: rp = row pair (2rp, 2rp+1), c = col within thread's 4
        ull acc[8][4];
        #pragma unroll
        for (int rp = 0; rp < 8; rp++)
            #pragma unroll
            for (int c = 0; c < 4; c++) acc[rp][c] = 0ull;
        const float4* wp = reinterpret_cast<const float4*>(fco_w + 2*CI*LL1) + tid;
        #pragma unroll 2
        for (int q = 0; q < 256; q++) {
            float4 wv = wp[(size_t)q*64];
            ull wc0 = pk(wv.x, wv.x), wc1 = pk(wv.y, wv.y);
            ull wc2 = pk(wv.z, wv.z), wc3 = pk(wv.w, wv.w);
            #pragma unroll
            for (int rr = 0; rr < 4; rr++) {
                ulonglong2 hp = *reinterpret_cast<const ulonglong2*>(&h1s[q*20 + 4*rr]);
                fma2(acc[2*rr+0][0], hp.x, wc0);
                fma2(acc[2*rr+0][1], hp.x, wc1);
                fma2(acc[2*rr+0][2], hp.x, wc2);
                fma2(acc[2*rr+0][3], hp.x, wc3);
                fma2(acc[2*rr+1][0], hp.y, wc0);
                fma2(acc[2*rr+1][1], hp.y, wc1);
                fma2(acc[2*rr+1][2], hp.y, wc2);
                fma2(acc[2*rr+1][3], hp.y, wc3);
            }
        }
        float4 bias = *(reinterpret_cast<const float4*>(fco_b) + tid);
        #pragma unroll
        for (int rp = 0; rp < 8; rp++) {
            float2 p0 = upk(acc[rp][0]), p1 = upk(acc[rp][1]);
            float2 p2 = upk(acc[rp][2]), p3 = upk(acc[rp][3]);
            float4 lo = make_float4(p0.x + bias.x, p1.x + bias.y, p2.x + bias.z, p3.x + bias.w);
            float4 hi = make_float4(p0.y + bias.x, p1.y + bias.y, p2.y + bias.z, p3.y + bias.w);
            *reinterpret_cast<float4*>(&d_po[(size_t)(row0 + 2*rp    )*LL1 + 4*tid]) = lo;
            *reinterpret_cast<float4*>(&d_po[(size_t)(row0 + 2*rp + 1)*LL1 + 4*tid]) = hi;
        }
    }
}

// ---------------- K8s: out = elu(d_po + hn @ fco_w[0:128]) ----------------
__global__ void __launch_bounds__(256) k8s(const float* __restrict__ fco_w,
                                           float* __restrict__ out)
{
    int c    = threadIdx.x;
    int row0 = blockIdx.x * RPB;
    __shared__ __align__(16) float cs[RPB*2*CI];   // 8 KB: hn columns only
    for (int idx = c; idx < RPB*2*CI; idx += 256) {
        int r = idx >> 7, q = idx & 127;
        cs[idx] = d_cat[(size_t)(row0+r)*CATW + q];
    }
    __syncthreads();
    ull acc[RPB];
    #pragma unroll
    for (int r = 0; r < RPB; r++) acc[r] = 0ull;
    #pragma unroll 2
    for (int qq = 0; qq < 2*CI/4; qq++) {
        float w0 = fco_w[(4*qq+0)*LL1 + c];
        float w1 = fco_w[(4*qq+1)*LL1 + c];
        float w2 = fco_w[(4*qq+2)*LL1 + c];
        float w3 = fco_w[(4*qq+3)*LL1 + c];
        ull wp0 = pk(w0, w1), wp1 = pk(w2, w3);
        #pragma unroll
        for (int r = 0; r < RPB; r++) {
            ulonglong2 cv = *reinterpret_cast<const ulonglong2*>(&cs[r*2*CI + 4*qq]);
            fma2(acc[r], cv.x, wp0);
            fma2(acc[r], cv.y, wp1);
        }
    }
    #pragma unroll
    for (int r = 0; r < RPB; r++) {
        float v = hsum2(acc[r]) + d_po[(size_t)(row0+r)*LL1 + c];
        out[(size_t)(row0+r)*LL1 + c] = v > 0.f ? v : expm1f(v);
    }
}

// ---------------- launch ----------------
extern "C" void kernel_launch(void* const* d_in, const int* in_sizes, int n_in,
                              void* d_out, int out_size)
{
    const float* x     = (const float*)d_in[0];
    const int*   adj   = (const int*)  d_in[1];
    const float* wedge = (const float*)d_in[2];
    const float* W     = (const float*)d_in[3];
    const float* a     = (const float*)d_in[4];
    const float* wfc_w = (const float*)d_in[5];
    const float* wfc_b = (const float*)d_in[6];
    const float* fc_w  = (const float*)d_in[7];
    const float* fc_b  = (const float*)d_in[8];
    const float* fcc_w = (const float*)d_in[9];
    const float* fcc_b = (const float*)d_in[10];
    const float* wih_f = (const float*)d_in[11];
    const float* whh_f = (const float*)d_in[12];
    const float* bih_f = (const float*)d_in[13];
    const float* bhh_f = (const float*)d_in[14];
    const float* wih_b = (const float*)d_in[15];
    const float* whh_b = (const float*)d_in[16];
    const float* bih_b = (const float*)d_in[17];
    const float* bhh_b = (const float*)d_in[18];
    const float* fco_w = (const float*)d_in[19];
    const float* fco_b = (const float*)d_in[20];
    float* out = (float*)d_out;

    K1    <<<128 + 1024, 256>>>(x, W, a, wedge, wfc_w, wfc_b, fc_w, fcc_w);
    k4b   <<<BB*NN,       NN>>>(adj, fc_b, fcc_b);
    kB    <<<512,        256>>>(wih_f, bih_f, bhh_f, wih_b, bih_b, bhh_b);
    k6p   <<<32 + 128,    64>>>(whh_f, whh_b, fco_w, fco_b);
    k8s   <<<BB*NN/RPB,  256>>>(fco_w, out);
}

// round 10
// speedup vs baseline: 1.0912x; 1.0862x over previous
#include <cuda_runtime.h>
#include <cuda_bf16.h>
#include <math.h>

#define BB   16
#define NN   128
#define FIN  128
#define FOUT 256
#define EOUT 64
#define BIN  14
#define BOUT 64
#define CI   64
#define LL1  256
#define CATW (2*CI + FOUT)   // 384
#define RPB  16

typedef unsigned long long ull;

// ---------------- scratch ----------------
__device__ float d_h  [BB*NN*FOUT];
__device__ float d_hc [BB*NN];
__device__ float d_s1 [BB*NN];
__device__ float d_s2 [BB*NN];
__device__ float d_ee [BB*NN*NN];
__device__ float d_att[BB*NN*NN];
__device__ float d_hn [BB*NN*NN];
__device__ float d_pre[2][BB*NN*CI];
__device__ float d_cat[BB*NN*CATW];

__device__ __forceinline__ float lrelu(float v) { return v > 0.f ? v : 0.01f * v; }

// ---- packed fp32x2 helpers ----
__device__ __forceinline__ ull pk(float lo, float hi) {
    ull r; asm("mov.b64 %0, {%1,%2};" : "=l"(r) : "f"(lo), "f"(hi)); return r;
}
__device__ __forceinline__ void fma2(ull& d, ull a, ull b) {
    asm("fma.rn.f32x2 %0, %1, %2, %3;" : "=l"(d) : "l"(a), "l"(b), "l"(d));
}
__device__ __forceinline__ ull add2(ull a, ull b) {
    ull r; asm("add.rn.f32x2 %0, %1, %2;" : "=l"(r) : "l"(a), "l"(b)); return r;
}
__device__ __forceinline__ float2 upk(ull v) {
    float2 f; asm("mov.b64 {%0,%1}, %2;" : "=f"(f.x), "=f"(f.y) : "l"(v)); return f;
}
__device__ __forceinline__ float hsum2(ull v) { float2 p = upk(v); return p.x + p.y; }
__device__ __forceinline__ float wred(float v) {
    #pragma unroll
    for (int off = 16; off > 0; off >>= 1) v += __shfl_xor_sync(0xffffffffu, v, off);
    return v;
}

// ============ K1: blocks [0,128): h=x@W, ha=h@a, s1/s2/hc ; [128,1152): wsum =======
__global__ void __launch_bounds__(256) K1(const float* __restrict__ x,
                                          const float* __restrict__ W,
                                          const float* __restrict__ a,
                                          const float* __restrict__ w_edge,
                                          const float* __restrict__ wfc_w,
                                          const float* __restrict__ wfc_b,
                                          const float* __restrict__ fc_w,
                                          const float* __restrict__ fcc_w) {
    __shared__ __align__(16) float smem_u[RPB*FIN + RPB*FOUT];   // 24 KB
    int tid = threadIdx.x;
    if (blockIdx.x < 128) {
        int f    = tid;
        int row0 = blockIdx.x * RPB;
        float* xs = smem_u;
        float* hs = smem_u + RPB*FIN;
        {
            const float4* src = reinterpret_cast<const float4*>(x + row0*FIN);
            float4* dst = reinterpret_cast<float4*>(xs);
            for (int t = f; t < RPB*FIN/4; t += 256) dst[t] = src[t];
        }
        __syncthreads();
        {
            ull acc[RPB];
            #pragma unroll
            for (int r = 0; r < RPB; r++) acc[r] = 0ull;
            #pragma unroll 2
            for (int kq = 0; kq < FIN/4; kq++) {
                float w0 = W[(4*kq+0)*FOUT + f];
                float w1 = W[(4*kq+1)*FOUT + f];
                float w2 = W[(4*kq+2)*FOUT + f];
                float w3 = W[(4*kq+3)*FOUT + f];
                ull wp0 = pk(w0, w1), wp1 = pk(w2, w3);
                #pragma unroll
                for (int r = 0; r < RPB; r++) {
                    ulonglong2 xv = *reinterpret_cast<const ulonglong2*>(&xs[r*FIN + 4*kq]);
                    fma2(acc[r], xv.x, wp0);
                    fma2(acc[r], xv.y, wp1);
                }
            }
            #pragma unroll
            for (int r = 0; r < RPB; r++) {
                float v = hsum2(acc[r]);
                hs[r*FOUT + f] = v;
                d_h[(row0+r)*FOUT + f] = v;
            }
        }
        __syncthreads();
        float* ha1s = xs;
        float* ha2s = xs + RPB*EOUT;
        {
            int g  = f >> 6;
            int kp = f & 63;
            int half = g >> 1;
            int r0 = (g & 1) * 8;
            const float* ap = a + half*FOUT*EOUT + kp;
            ull acc[8];
            #pragma unroll
            for (int r = 0; r < 8; r++) acc[r] = 0ull;
            #pragma unroll 2
            for (int fq = 0; fq < FOUT/4; fq++) {
                float w0 = ap[(4*fq+0)*EOUT];
                float w1 = ap[(4*fq+1)*EOUT];
                float w2 = ap[(4*fq+2)*EOUT];
                float w3 = ap[(4*fq+3)*EOUT];
                ull wp0 = pk(w0, w1), wp1 = pk(w2, w3);
                #pragma unroll
                for (int r = 0; r < 8; r++) {
                    ulonglong2 hv = *reinterpret_cast<const ulonglong2*>(&hs[(r0+r)*FOUT + 4*fq]);
                    fma2(acc[r], hv.x, wp0);
                    fma2(acc[r], hv.y, wp1);
                }
            }
            float* has = half ? ha2s : ha1s;
            #pragma unroll
            for (int r = 0; r < 8; r++)
                has[(r0 + r)*EOUT + kp] = hsum2(acc[r]);
        }
        __syncthreads();
        {
            int warp = tid >> 5, lane = tid & 31;
            if (warp < 4) {
                float fw0 = fc_w[lane], fw1 = fc_w[32 + lane];
                #pragma unroll
                for (int rr = 0; rr < 4; rr++) {
                    int r = warp*4 + rr;
                    float v = lrelu(ha1s[r*EOUT + lane]      + ha2s[r*EOUT + lane])      * fw0
                            + lrelu(ha1s[r*EOUT + 32 + lane] + ha2s[r*EOUT + 32 + lane]) * fw1;
                    v = wred(v);
                    if (lane == 0) d_s1[row0 + r] = v;
                }
            } else if (warp < 6) {
                float fw0 = fc_w[lane], fw1 = fc_w[32 + lane];
                int b  = row0 >> 7;
                int j0 = ((row0 & 127) >> 1);
                #pragma unroll
                for (int q = 0; q < 4; q++) {
                    int jj = (warp - 4)*4 + q;
                    int r1 = 2*jj, r2 = 2*jj + 1;
                    float v = lrelu(ha1s[r1*EOUT + lane]      + ha2s[r2*EOUT + lane])      * fw0
                            + lrelu(ha1s[r1*EOUT + 32 + lane] + ha2s[r2*EOUT + 32 + lane]) * fw1;
                    v = wred(v);
                    if (lane == 0) {
                        d_s2[b*NN + j0 + jj]      = v;
                        d_s2[b*NN + j0 + jj + 64] = v;
                    }
                }
            } else {
                #pragma unroll
                for (int rr = 0; rr < 8; rr++) {
                    int r = (warp - 6)*8 + rr;
                    float v = 0.f;
                    #pragma unroll
                    for (int q = 0; q < 8; q++)
                        v += hs[r*FOUT + lane + 32*q] * fcc_w[lane + 32*q];
                    v = wred(v);
                    if (lane == 0) d_hc[row0 + r] = v;
                }
            }
        }
    } else {
        int w    = blockIdx.x - 128;
        int row0 = w * 2;
        float* wes = smem_u;
        float* wf  = smem_u + 2*NN*BIN;
        float* wb  = wf + BIN*BOUT;
        float* f2  = wb + BOUT;
        {
            const float4* src = reinterpret_cast<const float4*>(w_edge + (size_t)row0*NN*BIN);
            float4* dst = reinterpret_cast<float4*>(wes);
            for (int t = tid; t < 2*NN*BIN/4; t += 256) dst[t] = src[t];
        }
        for (int t = tid; t < BIN*BOUT; t += 256) wf[t] = wfc_w[t];
        if (tid < BOUT) { wb[tid] = wfc_b[tid]; f2[tid] = fc_w[BOUT + tid]; }
        __syncthreads();

        int r = tid >> 7, j = tid & 127;
        ull we2[BIN];
        #pragma unroll
        for (int m = 0; m < BIN; m++) { float v = wes[(r*NN + j)*BIN + m]; we2[m] = pk(v, v); }

        const ulonglong2* wfp = reinterpret_cast<const ulonglong2*>(wf);
        const ulonglong2* wbp = reinterpret_cast<const ulonglong2*>(wb);
        const float4*     f2p = reinterpret_cast<const float4*>(f2);
        float wsum = 0.f;
        #pragma unroll 4
        for (int kq = 0; kq < BOUT/4; kq++) {
            ulonglong2 aq = wbp[kq];
            ull a0 = aq.x, a1 = aq.y;
            #pragma unroll
            for (int m = 0; m < BIN; m++) {
                ulonglong2 w2 = wfp[m*16 + kq];
                fma2(a0, we2[m], w2.x);
                fma2(a1, we2[m], w2.y);
            }
            float2 p0 = upk(a0), p1 = upk(a1);
            float4 fv = f2p[kq];
            wsum += lrelu(p0.x)*fv.x + lrelu(p0.y)*fv.y + lrelu(p1.x)*fv.z + lrelu(p1.y)*fv.w;
        }
        d_ee[(row0 + r)*NN + j] = wsum;
    }
}

// ---------------- K4b: mask + softmax + hn ----------------
__global__ void __launch_bounds__(NN) k4b(const int* __restrict__ adj,
                                          const float* __restrict__ fc_b,
                                          const float* __restrict__ fcc_b)
{
    int bi = blockIdx.x;
    int b = bi >> 7, i = bi & 127;
    int j = threadIdx.x;
    float contrib = (i < 64) ? d_s1[b*NN + 2*i + (j >= 64 ? 1 : 0)]
                             : d_s2[b*NN + j];
    float e = d_ee[(size_t)bi*NN + j] + contrib + fc_b[0];
    if (adj[(size_t)bi*NN + j] <= 0) e = -9e15f;

    int lane = j & 31, wid = j >> 5;
    float mx = e;
    #pragma unroll
    for (int off = 16; off > 0; off >>= 1) mx = fmaxf(mx, __shfl_xor_sync(0xffffffffu, mx, off));
    __shared__ float wredm[4], wreds[4];
    if (lane == 0) wredm[wid] = mx;
    __syncthreads();
    mx = fmaxf(fmaxf(wredm[0], wredm[1]), fmaxf(wredm[2], wredm[3]));
    float ex = __expf(e - mx);
    float s = ex;
    #pragma unroll
    for (int off = 16; off > 0; off >>= 1) s += __shfl_xor_sync(0xffffffffu, s, off);
    if (lane == 0) wreds[wid] = s;
    __syncthreads();
    s = (wreds[0] + wreds[1]) + (wreds[2] + wreds[3]);
    float att = ex / s;

    d_att[(size_t)bi*NN + j] = att;
    d_hn [(size_t)bi*NN + j] = lrelu(att * d_hc[bi] + fcc_b[0]);
}

// ---------------- KB: blocks [0,256): h1 = att@h (8 rows); [256,512): RNN pre ------
__global__ void __launch_bounds__(256) kB(
    const float* __restrict__ wih_f, const float* __restrict__ bih_f,
    const float* __restrict__ bhh_f,
    const float* __restrict__ wih_b, const float* __restrict__ bih_b,
    const float* __restrict__ bhh_b)
{
    __shared__ __align__(16) float pool[NN*65 + RPB*NN];
    int tid = threadIdx.x;
    if (blockIdx.x < 256) {
        int bx = blockIdx.x;
        int b  = bx >> 4;
        int i0 = (bx & 15) * 8;
        float* as = pool;
        for (int idx = tid; idx < 8*NN; idx += 256)
            as[idx] = d_att[((size_t)b*NN + i0)*NN + idx];
        __syncthreads();
        ull acc[8];
        #pragma unroll
        for (int r = 0; r < 8; r++) acc[r] = 0ull;
        const float* hb = d_h + b*NN*FOUT;
        #pragma unroll 4
        for (int jq = 0; jq < NN/4; jq++) {
            float h0 = hb[(4*jq+0)*FOUT + tid];
            float h1 = hb[(4*jq+1)*FOUT + tid];
            float h2 = hb[(4*jq+2)*FOUT + tid];
            float h3 = hb[(4*jq+3)*FOUT + tid];
            ull hp0 = pk(h0, h1), hp1 = pk(h2, h3);
            #pragma unroll
            for (int r = 0; r < 8; r++) {
                ulonglong2 av = *reinterpret_cast<const ulonglong2*>(&as[r*NN + 4*jq]);
                fma2(acc[r], av.x, hp0);
                fma2(acc[r], av.y, hp1);
            }
        }
        #pragma unroll
        for (int r = 0; r < 8; r++)
            d_cat[(b*NN + i0 + r)*CATW + 2*CI + tid] = hsum2(acc[r]);
    } else {
        int bx2 = blockIdx.x - 256;
        int dir = bx2 >> 7;
        int rem = bx2 & 127;
        int b   = rem >> 3;
        int t0  = (rem & 7) * RPB;
        int c    = tid & 63;
        int quad = tid >> 6;
        float* wT = pool;
        float* xs = pool + NN*65;
        const float* wih = dir ? wih_b : wih_f;
        for (int idx = tid; idx < CI*NN; idx += 256) {
            int cc = idx >> 7, q = idx & 127;
            wT[q*65 + cc] = wih[idx];
        }
        for (int idx = tid; idx < RPB*NN; idx += 256) {
            int r = idx >> 7, q = idx & 127;
            int src = dir ? (NN-1 - (t0+r)) : (t0+r);
            xs[r*NN + q] = d_hn[(b*NN + src)*NN + q];
        }
        __syncthreads();
        float bias = dir ? (bih_b[c] + bhh_b[c]) : (bih_f[c] + bhh_f[c]);
        float acc[4];
        #pragma unroll
        for (int r = 0; r < 4; r++) acc[r] = bias;
        #pragma unroll 2
        for (int qq = 0; qq < NN/4; qq++) {
            float w0 = wT[(4*qq+0)*65 + c];
            float w1 = wT[(4*qq+1)*65 + c];
            float w2 = wT[(4*qq+2)*65 + c];
            float w3 = wT[(4*qq+3)*65 + c];
            #pragma unroll
            for (int r = 0; r < 4; r++) {
                float4 xv = *reinterpret_cast<const float4*>(&xs[(quad*4+r)*NN + 4*qq]);
                acc[r] = fmaf(xv.x, w0, fmaf(xv.y, w1, fmaf(xv.z, w2, fmaf(xv.w, w3, acc[r]))));
            }
        }
        #pragma unroll
        for (int r = 0; r < 4; r++)
            d_pre[dir][(b*NN + t0 + quad*4 + r)*CI + c] = acc[r];
    }
}

// ---------------- K6: serial RNN — smem-only loop, bulk writeback after -----------
__global__ void __launch_bounds__(64) k6_rnn(const float* __restrict__ whh_f,
                                             const float* __restrict__ whh_b)
{
    __shared__ __align__(16) float ps[NN*CI];      // 32 KB: pre slab -> lrelu out
    __shared__ __align__(16) float hbuf[2][CI];
    int dir = blockIdx.x >> 4;
    int b   = blockIdx.x & 15;
    int j   = threadIdx.x;
    const float* whh = dir ? whh_b : whh_f;
    ull w2[32];
    {
        const float4* wr = reinterpret_cast<const float4*>(whh + j*64);
        #pragma unroll
        for (int kk = 0; kk < 16; kk++) {
            float4 wv = wr[kk];
            w2[2*kk]   = pk(wv.x, wv.y);
            w2[2*kk+1] = pk(wv.z, wv.w);
        }
    }
    {
        const float4* src = reinterpret_cast<const float4*>(d_pre[dir] + (size_t)b*NN*CI);
        float4* dst = reinterpret_cast<float4*>(ps);
        #pragma unroll
        for (int t = j; t < NN*CI/4; t += 64) dst[t] = src[t];
    }
    hbuf[0][j] = 0.f;
    __syncthreads();
    #pragma unroll 1
    for (int t = 0; t < NN; t++) {
        int cur = t & 1;
        float pv = ps[t*CI + j];
        const ulonglong2* h4 = reinterpret_cast<const ulonglong2*>(hbuf[cur]);
        ull a0 = 0ull, a1 = 0ull, a2 = 0ull, a3 = 0ull;
        #pragma unroll
        for (int kk = 0; kk < 16; kk++) {
            ulonglong2 hv = h4[kk];
            ull& acc = (kk & 3) == 0 ? a0 : ((kk & 3) == 1 ? a1 : ((kk & 3) == 2 ? a2 : a3));
            fma2(acc, w2[2*kk],   hv.x);
            fma2(acc, w2[2*kk+1], hv.y);
        }
        float dot = hsum2(add2(add2(a0, a1), add2(a2, a3)));
        float sarg = pv + dot;
        float ee = __expf(2.f * sarg);
        float th = 1.f - __fdividef(2.f, ee + 1.f);
        hbuf[cur ^ 1][j] = th;
        ps[t*CI + j] = lrelu(th);        // overwrite consumed slot (STS only)
        __syncthreads();
    }
    // bulk coalesced writeback (one contiguous 256B row per iteration)
    float* base = d_cat + (size_t)(b*NN)*CATW + dir*CI;
    #pragma unroll 4
    for (int t = 0; t < NN; t++) {
        int tt = dir ? (NN-1 - t) : t;
        base[tt*CATW + j] = ps[t*CI + j];
    }
}

// ---------------- K8: out = elu(cat @ fco_w + fco_b) ----------------
__global__ void __launch_bounds__(256) k8_out(const float* __restrict__ fco_w,
                                              const float* __restrict__ fco_b,
                                              float* __restrict__ out)
{
    int c    = threadIdx.x;
    int row0 = blockIdx.x * RPB;
    __shared__ __align__(16) float cs[RPB*CATW];
    {
        const float4* src = reinterpret_cast<const float4*>(d_cat + row0*CATW);
        float4* dst = reinterpret_cast<float4*>(cs);
        for (int t = c; t < RPB*CATW/4; t += 256) dst[t] = src[t];
    }
    __syncthreads();
    float bias = fco_b[c];
    ull acc[RPB];
    #pragma unroll
    for (int r = 0; r < RPB; r++) acc[r] = 0ull;
    #pragma unroll 4
    for (int qq = 0; qq < CATW/4; qq++) {
        float w0 = fco_w[(4*qq+0)*LL1 + c];
        float w1 = fco_w[(4*qq+1)*LL1 + c];
        float w2 = fco_w[(4*qq+2)*LL1 + c];
        float w3 = fco_w[(4*qq+3)*LL1 + c];
        ull wp0 = pk(w0, w1), wp1 = pk(w2, w3);
        #pragma unroll
        for (int r = 0; r < RPB; r++) {
            ulonglong2 cv = *reinterpret_cast<const ulonglong2*>(&cs[r*CATW + 4*qq]);
            fma2(acc[r], cv.x, wp0);
            fma2(acc[r], cv.y, wp1);
        }
    }
    #pragma unroll
    for (int r = 0; r < RPB; r++) {
        float v = hsum2(acc[r]) + bias;
        out[(row0+r)*LL1 + c] = v > 0.f ? v : expm1f(v);
    }
}

// ---------------- launch ----------------
extern "C" void kernel_launch(void* const* d_in, const int* in_sizes, int n_in,
                              void* d_out, int out_size)
{
    const float* x     = (const float*)d_in[0];
    const int*   adj   = (const int*)  d_in[1];
    const float* wedge = (const float*)d_in[2];
    const float* W     = (const float*)d_in[3];
    const float* a     = (const float*)d_in[4];
    const float* wfc_w = (const float*)d_in[5];
    const float* wfc_b = (const float*)d_in[6];
    const float* fc_w  = (const float*)d_in[7];
    const float* fc_b  = (const float*)d_in[8];
    const float* fcc_w = (const float*)d_in[9];
    const float* fcc_b = (const float*)d_in[10];
    const float* wih_f = (const float*)d_in[11];
    const float* whh_f = (const float*)d_in[12];
    const float* bih_f = (const float*)d_in[13];
    const float* bhh_f = (const float*)d_in[14];
    const float* wih_b = (const float*)d_in[15];
    const float* whh_b = (const float*)d_in[16];
    const float* bih_b = (const float*)d_in[17];
    const float* bhh_b = (const float*)d_in[18];
    const float* fco_w = (const float*)d_in[19];
    const float* fco_b = (const float*)d_in[20];
    float* out = (float*)d_out;

    K1    <<<128 + 1024, 256>>>(x, W, a, wedge, wfc_w, wfc_b, fc_w, fcc_w);
    k4b   <<<BB*NN,       NN>>>(adj, fc_b, fcc_b);
    kB    <<<512,        256>>>(wih_f, bih_f, bhh_f, wih_b, bih_b, bhh_b);
    k6_rnn<<<2*BB,        64>>>(whh_f, whh_b);
    k8_out<<<BB*NN/RPB,  256>>>(fco_w, fco_b, out);
}